// round 3
// baseline (speedup 1.0000x reference)
#include <cuda_runtime.h>

#define NN 100000
#define NE 3200000
#define KF 1433
#define NH 16
#define NO 7

// ---------------- scratch (device globals; no allocation allowed) ----------
__device__ float g_deg_out[NN];               // becomes norm_src after norm_kernel
__device__ float g_deg_in[NN];                // becomes norm_dst after norm_kernel
__device__ __align__(16) float g_x1[NN * 16];
__device__ __align__(16) float g_m1[NN * 16];
__device__ __align__(16) float g_x2[NN * 8];
__device__ __align__(16) float g_m2[NN * 8];
__device__ int g_src[NE];
__device__ int g_dst[NE];
__device__ int g_is64;

// ---------------- small PTX helpers ----------------------------------------
__device__ __forceinline__ unsigned long long fma2(unsigned long long a,
                                                   unsigned long long b,
                                                   unsigned long long c) {
    unsigned long long d;
    asm("fma.rn.f32x2 %0, %1, %2, %3;" : "=l"(d) : "l"(a), "l"(b), "l"(c));
    return d;
}
__device__ __forceinline__ unsigned long long pack2(float x) {
    unsigned long long d;
    asm("mov.b64 %0, {%1, %1};" : "=l"(d) : "f"(x));
    return d;
}
__device__ __forceinline__ float2 unpack2(unsigned long long v) {
    float2 f;
    asm("mov.b64 {%0, %1}, %2;" : "=f"(f.x), "=f"(f.y) : "l"(v));
    return f;
}
__device__ __forceinline__ void red4(float* p, float4 v) {
    asm volatile("red.global.add.v4.f32 [%0], {%1, %2, %3, %4};"
                 :: "l"(p), "f"(v.x), "f"(v.y), "f"(v.z), "f"(v.w)
                 : "memory");
}
// 4-byte cp.async: only 4B alignment required (feat rows are 4 mod 16!).
// src-size operand: 4 = copy, 0 = hardware zero-fill (no global access).
__device__ __forceinline__ void cp4(unsigned int saddr, const void* gaddr, int srcbytes) {
    asm volatile("cp.async.ca.shared.global [%0], [%1], 4, %2;"
                 :: "r"(saddr), "l"(gaddr), "r"(srcbytes));
}

// ---------------- edge dtype detect ----------------------------------------
// int64 edges: every odd 32-bit word (high half) is 0. int32 edges: odd words
// are random node ids in [0, 100000) — all-32-zero has probability ~1e-160.
__global__ void detect_kernel(const void* ei) {
    const int* w = (const int*)ei;
    int t = threadIdx.x;
    int v = w[2 * t + 1];
    unsigned b = __ballot_sync(0xffffffffu, v != 0);
    if (t == 0) g_is64 = (b == 0) ? 1 : 0;
}

// ---------------- fused convert + degree histogram (one edge pass) ---------
__global__ void convdeg_kernel(const void* ei) {
    int e = blockIdx.x * blockDim.x + threadIdx.x;
    if (e >= NE) return;
    int s, d;
    if (g_is64) {
        const long long* p = (const long long*)ei;
        s = (int)p[e];
        d = (int)p[NE + e];
    } else {
        const int* p = (const int*)ei;
        s = p[e];
        d = p[NE + e];
    }
    g_src[e] = s;
    g_dst[e] = d;
    atomicAdd(&g_deg_out[s], 1.0f);
    atomicAdd(&g_deg_in[d], 1.0f);
}

__global__ void norm_kernel() {
    int i = blockIdx.x * blockDim.x + threadIdx.x;
    if (i >= NN) return;
    g_deg_out[i] = rsqrtf(fmaxf(g_deg_out[i], 1.0f));
    g_deg_in[i]  = rsqrtf(fmaxf(g_deg_in[i], 1.0f));
}

// ---------------- GEMM1: x1_raw = feat @ W1  [100k x 16] -------------------
// (norm_src scaling deferred to scale_x1 so this kernel has NO edge deps
//  and can overlap the edge-processing stream.)
// Block: 256 nodes x 16 cols. 2-stage cp.async (4B ops) pipeline, 32-k chunks.
// A stage: 256 rows x 32 floats, pitch 33 (conflict-free).
// Thread t: nodes nl0=t&~1, nl0+1; column half ch=t&1 (8 cols).
// 8 packed fma.rn.f32x2 per k per thread.
#define APITCH 33
#define A_STAGE (256 * APITCH)           // 8448 floats
#define W_STAGE 512                      // 32 x 16
#define SMEM_FLOATS (2 * A_STAGE + 2 * W_STAGE)
#define SMEM_BYTES (SMEM_FLOATS * 4)     // 71680 B

__global__ void __launch_bounds__(256, 3) gemm1_kernel(const float* __restrict__ feat,
                                                       const float* __restrict__ W1) {
    extern __shared__ float sm[];
    float* Abuf[2] = { sm, sm + A_STAGE };
    float* Wbuf[2] = { sm + 2 * A_STAGE, sm + 2 * A_STAGE + W_STAGE };

    const int tid = threadIdx.x;
    const int node0 = blockIdx.x * 256;
    const int nl0 = tid & ~1;   // nodes nl0, nl0+1
    const int ch  = tid & 1;    // column half (8 cols)

    // cp.async mapping (A): elem idx = tid + 256*i, i<32
    //   col = tid & 31 (constant), row = (tid>>5) + 8*i
    const int acol  = tid & 31;
    const int arow0 = tid >> 5;
    // cp.async mapping (W): elems tid, tid+256: row = idx>>4, col = idx&15
    const int wrow0 = tid >> 4, wcol = tid & 15;
    const int wrow1 = (tid + 256) >> 4;

    unsigned long long acc[2][4];
#pragma unroll
    for (int i = 0; i < 2; i++)
#pragma unroll
        for (int j = 0; j < 4; j++) acc[i][j] = 0ull;

    unsigned int aS[2], wS[2];
    aS[0] = (unsigned int)__cvta_generic_to_shared(Abuf[0] + arow0 * APITCH + acol);
    aS[1] = (unsigned int)__cvta_generic_to_shared(Abuf[1] + arow0 * APITCH + acol);
    wS[0] = (unsigned int)__cvta_generic_to_shared(Wbuf[0] + wrow0 * 16 + wcol);
    wS[1] = (unsigned int)__cvta_generic_to_shared(Wbuf[1] + wrow0 * 16 + wcol);

    const int NCHUNK = (KF + 31) / 32;   // 45

#define ISSUE_STAGE(b, cc)                                                        \
    {                                                                             \
        const int k0 = (cc) * 32;                                                 \
        const int kcol = k0 + acol;                                               \
        const int kb = (kcol < KF) ? 4 : 0;                                       \
        _Pragma("unroll")                                                         \
        for (int i = 0; i < 32; i++) {                                            \
            int r = arow0 + 8 * i;                                                \
            int bytes = (node0 + r < NN) ? kb : 0;                                \
            cp4(aS[b] + (unsigned)(8 * i * APITCH) * 4u,                          \
                feat + (size_t)(node0 + r) * KF + kcol, bytes);                   \
        }                                                                         \
        cp4(wS[b], W1 + (k0 + wrow0) * NH + wcol, (k0 + wrow0 < KF) ? 4 : 0);     \
        cp4(wS[b] + 1024u, W1 + (k0 + wrow1) * NH + wcol,                         \
            (k0 + wrow1 < KF) ? 4 : 0);                                           \
        asm volatile("cp.async.commit_group;");                                   \
    }

    ISSUE_STAGE(0, 0);

    for (int c = 0; c < NCHUNK; c++) {
        const int buf = c & 1;
        if (c + 1 < NCHUNK) {
            ISSUE_STAGE(buf ^ 1, c + 1);
            asm volatile("cp.async.wait_group 1;");
        } else {
            asm volatile("cp.async.wait_group 0;");
        }
        __syncthreads();

        const float* A = Abuf[buf];
        const float* W = Wbuf[buf];
#pragma unroll
        for (int k = 0; k < 32; k++) {
            float a0 = A[nl0 * APITCH + k];
            float a1 = A[(nl0 + 1) * APITCH + k];
            const float* wp = W + k * 16 + ch * 8;
            ulonglong2 wA = *(const ulonglong2*)wp;        // cols 0..3 of half
            ulonglong2 wB = *(const ulonglong2*)(wp + 4);  // cols 4..7 of half
            unsigned long long A0 = pack2(a0);
            unsigned long long A1 = pack2(a1);
            acc[0][0] = fma2(A0, wA.x, acc[0][0]);
            acc[0][1] = fma2(A0, wA.y, acc[0][1]);
            acc[0][2] = fma2(A0, wB.x, acc[0][2]);
            acc[0][3] = fma2(A0, wB.y, acc[0][3]);
            acc[1][0] = fma2(A1, wA.x, acc[1][0]);
            acc[1][1] = fma2(A1, wA.y, acc[1][1]);
            acc[1][2] = fma2(A1, wB.x, acc[1][2]);
            acc[1][3] = fma2(A1, wB.y, acc[1][3]);
        }
        __syncthreads();
    }

    // epilogue: store RAW x1 (2 nodes x 8 cols); scaling happens in scale_x1
#pragma unroll
    for (int i = 0; i < 2; i++) {
        int n = node0 + nl0 + i;
        if (n < NN) {
            float2 v0 = unpack2(acc[i][0]);
            float2 v1 = unpack2(acc[i][1]);
            float2 v2 = unpack2(acc[i][2]);
            float2 v3 = unpack2(acc[i][3]);
            float4* xp = (float4*)(g_x1 + n * 16 + ch * 8);
            xp[0] = make_float4(v0.x, v0.y, v1.x, v1.y);
            xp[1] = make_float4(v2.x, v2.y, v3.x, v3.y);
        }
    }
#undef ISSUE_STAGE
}

// ---------------- scale x1 by norm_src (join point of the two streams) -----
__global__ void scale_x1_kernel() {
    int i = blockIdx.x * blockDim.x + threadIdx.x;   // float4 index
    if (i >= NN * 4) return;
    int n = i >> 2;
    float ns = g_deg_out[n];
    float4* p = (float4*)g_x1 + i;
    float4 v = *p;
    v.x *= ns; v.y *= ns; v.z *= ns; v.w *= ns;
    *p = v;
}

// ---------------- scatter layer 1: m1[dst] += x1[src] (16 floats) ----------
__global__ void scatter1_kernel() {
    int e = blockIdx.x * blockDim.x + threadIdx.x;
    if (e >= NE) return;
    int s = g_src[e];
    int d = g_dst[e];
    const float4* x = (const float4*)(g_x1 + s * 16);
    float* m = g_m1 + d * 16;
    float4 v0 = x[0], v1 = x[1], v2 = x[2], v3 = x[3];
    red4(m, v0);
    red4(m + 4, v1);
    red4(m + 8, v2);
    red4(m + 12, v3);
}

// ---------------- mid: h = relu(m1*nd + b1); x2 = (h*ns) @ W2 (pad to 8) ---
__global__ void mid_kernel(const float* __restrict__ b1, const float* __restrict__ W2) {
    int n = blockIdx.x * blockDim.x + threadIdx.x;
    if (n >= NN) return;
    float nd = g_deg_in[n];   // norm_dst
    float ns = g_deg_out[n];  // norm_src
    float h[16];
    const float4* mp = (const float4*)(g_m1 + n * 16);
#pragma unroll
    for (int q = 0; q < 4; q++) {
        float4 v = mp[q];
        h[4 * q + 0] = fmaxf(v.x * nd + __ldg(&b1[4 * q + 0]), 0.0f);
        h[4 * q + 1] = fmaxf(v.y * nd + __ldg(&b1[4 * q + 1]), 0.0f);
        h[4 * q + 2] = fmaxf(v.z * nd + __ldg(&b1[4 * q + 2]), 0.0f);
        h[4 * q + 3] = fmaxf(v.w * nd + __ldg(&b1[4 * q + 3]), 0.0f);
    }
    float o[8];
#pragma unroll
    for (int c = 0; c < NO; c++) {
        float s = 0.0f;
#pragma unroll
        for (int j = 0; j < 16; j++) s = fmaf(h[j], __ldg(&W2[j * NO + c]), s);
        o[c] = ns * s;
    }
    o[7] = 0.0f;
    float4* xp = (float4*)(g_x2 + n * 8);
    xp[0] = make_float4(o[0], o[1], o[2], o[3]);
    xp[1] = make_float4(o[4], o[5], o[6], o[7]);
}

// ---------------- scatter layer 2: m2[dst] += x2[src] (8 floats) -----------
__global__ void scatter2_kernel() {
    int e = blockIdx.x * blockDim.x + threadIdx.x;
    if (e >= NE) return;
    int s = g_src[e];
    int d = g_dst[e];
    const float4* x = (const float4*)(g_x2 + s * 8);
    float* m = g_m2 + d * 8;
    float4 v0 = x[0], v1 = x[1];
    red4(m, v0);
    red4(m + 4, v1);
}

// ---------------- output: out = m2*nd + b2 ---------------------------------
__global__ void out_kernel(const float* __restrict__ b2, float* __restrict__ out) {
    int i = blockIdx.x * blockDim.x + threadIdx.x;
    if (i >= NN * NO) return;
    int n = i / NO;
    int c = i - n * NO;
    out[i] = g_m2[n * 8 + c] * g_deg_in[n] + __ldg(&b2[c]);
}

// ---------------- launch ---------------------------------------------------
extern "C" void kernel_launch(void* const* d_in, const int* in_sizes, int n_in,
                              void* d_out, int out_size) {
    const float* feat = (const float*)d_in[0];
    const void* ei    = d_in[1];
    const float* W1   = (const float*)d_in[2];
    const float* b1   = (const float*)d_in[3];
    const float* W2   = (const float*)d_in[4];
    const float* b2   = (const float*)d_in[5];
    float* out        = (float*)d_out;

    // one-time host-side setup (first call is the non-captured correctness
    // run; no device memory is allocated here)
    static cudaStream_t s2 = 0;
    static cudaEvent_t evA = 0, evB = 0;
    if (!s2) {
        cudaStreamCreateWithFlags(&s2, cudaStreamNonBlocking);
        cudaEventCreateWithFlags(&evA, cudaEventDisableTiming);
        cudaEventCreateWithFlags(&evB, cudaEventDisableTiming);
        cudaFuncSetAttribute(gemm1_kernel,
                             cudaFuncAttributeMaxDynamicSharedMemorySize, SMEM_BYTES);
    }

    void *pdo, *pdi, *pm1, *pm2;
    cudaGetSymbolAddress(&pdo, g_deg_out);
    cudaGetSymbolAddress(&pdi, g_deg_in);
    cudaGetSymbolAddress(&pm1, g_m1);
    cudaGetSymbolAddress(&pm2, g_m2);
    cudaMemsetAsync(pdo, 0, (size_t)NN * sizeof(float));
    cudaMemsetAsync(pdi, 0, (size_t)NN * sizeof(float));
    cudaMemsetAsync(pm1, 0, (size_t)NN * 16 * sizeof(float));
    cudaMemsetAsync(pm2, 0, (size_t)NN * 8 * sizeof(float));

    const int TB = 256;
    const int EBLK = NE / TB;             // 12500 (exact)
    const int NBLK = (NN + TB - 1) / TB;  // 391

    // fork: edge chain on s2, gemm1 on main stream
    cudaEventRecord(evA, 0);
    cudaStreamWaitEvent(s2, evA, 0);
    detect_kernel<<<1, 32, 0, s2>>>(ei);
    convdeg_kernel<<<EBLK, TB, 0, s2>>>(ei);
    norm_kernel<<<NBLK, TB, 0, s2>>>();
    cudaEventRecord(evB, s2);

    gemm1_kernel<<<NBLK, TB, SMEM_BYTES>>>(feat, W1);

    // join
    cudaStreamWaitEvent(0, evB, 0);
    scale_x1_kernel<<<(NN * 4 + TB - 1) / TB, TB>>>();
    scatter1_kernel<<<EBLK, TB>>>();
    mid_kernel<<<NBLK, TB>>>(b1, W2);
    scatter2_kernel<<<EBLK, TB>>>();
    out_kernel<<<(NN * NO + TB - 1) / TB, TB>>>(b2, out);
}

// round 7
// speedup vs baseline: 1.2997x; 1.2997x over previous
#include <cuda_runtime.h>

#define NN 100000
#define NE 3200000
#define KF 1433
#define NH 16
#define NO 7

// ---------------- scratch (device globals; no allocation allowed) ----------
__device__ float g_deg_out[NN];               // becomes norm_src after norm_kernel
__device__ float g_deg_in[NN];                // becomes norm_dst after norm_kernel
__device__ __align__(16) float g_x1[NN * 16];   // RAW feat@W1 (unscaled)
__device__ __align__(16) float g_m1[NN * 16];
__device__ __align__(16) float g_x2[NN * 8];
__device__ __align__(16) float g_m2[NN * 8];
__device__ int g_src[NE];
__device__ int g_dst[NE];
__device__ int g_is64;

// ---------------- PTX helpers ----------------------------------------------
__device__ __forceinline__ void red4(float* p, float4 v) {
    asm volatile("red.global.add.v4.f32 [%0], {%1, %2, %3, %4};"
                 :: "l"(p), "f"(v.x), "f"(v.y), "f"(v.z), "f"(v.w)
                 : "memory");
}
__device__ __forceinline__ unsigned to_tf32(float x) {
    unsigned r;
    asm("cvt.rna.tf32.f32 %0, %1;" : "=r"(r) : "f"(x));
    return r;
}
// 3xTF32 split: x ~= hi + lo, both representable in tf32
__device__ __forceinline__ void split_tf32(float x, unsigned& hi, unsigned& lo) {
    hi = to_tf32(x);
    lo = to_tf32(x - __uint_as_float(hi));
}
__device__ __forceinline__ void mma_tf32(float* c, const unsigned* a, const unsigned* b) {
    asm volatile("mma.sync.aligned.m16n8k8.row.col.f32.tf32.tf32.f32 "
                 "{%0,%1,%2,%3}, {%4,%5,%6,%7}, {%8,%9}, {%0,%1,%2,%3};"
                 : "+f"(c[0]), "+f"(c[1]), "+f"(c[2]), "+f"(c[3])
                 : "r"(a[0]), "r"(a[1]), "r"(a[2]), "r"(a[3]),
                   "r"(b[0]), "r"(b[1]));
}

// ---------------- edge dtype detect ----------------------------------------
// int64 edges: every odd 32-bit word (high half) is 0. int32 edges: odd words
// are random node ids in [0, 100000) — all-32-zero has probability ~1e-160.
__global__ void detect_kernel(const void* ei) {
    const int* w = (const int*)ei;
    int t = threadIdx.x;
    int v = w[2 * t + 1];
    unsigned b = __ballot_sync(0xffffffffu, v != 0);
    if (t == 0) g_is64 = (b == 0) ? 1 : 0;
}

// ---------------- fused convert + degree histogram (one edge pass) ---------
__global__ void convdeg_kernel(const void* ei) {
    int e = blockIdx.x * blockDim.x + threadIdx.x;
    if (e >= NE) return;
    int s, d;
    if (g_is64) {
        const long long* p = (const long long*)ei;
        s = (int)p[e];
        d = (int)p[NE + e];
    } else {
        const int* p = (const int*)ei;
        s = p[e];
        d = p[NE + e];
    }
    g_src[e] = s;
    g_dst[e] = d;
    atomicAdd(&g_deg_out[s], 1.0f);
    atomicAdd(&g_deg_in[d], 1.0f);
}

__global__ void norm_kernel() {
    int i = blockIdx.x * blockDim.x + threadIdx.x;
    if (i >= NN) return;
    g_deg_out[i] = rsqrtf(fmaxf(g_deg_out[i], 1.0f));
    g_deg_in[i]  = rsqrtf(fmaxf(g_deg_in[i], 1.0f));
}

// ---------------- GEMM1: x1_raw = feat @ W1  [100k x 16], 3xTF32 mma -------
// Block 256 threads = 8 warps; block tile 256 nodes x 16 cols; k-chunk 32.
// Warp w: nodes [32w, 32w+32) = 2 m16 tiles; cols = 2 n8 tiles.
// A smem: 256 rows x 32 k, pitch 36 -> fragment LDS addr ~ 4g+tg, conflict-free.
// Loads: coalesced LDG.32 bursts (4B-aligned feat rows) + STS.128, 2-stage.
#define APITCH 36
#define A_ST (256 * APITCH)              // 9216 floats per stage
#define W_ST 512                         // 32 x 16
#define SMEM_FLOATS (2 * A_ST + 2 * W_ST)
#define SMEM_BYTES (SMEM_FLOATS * 4)     // 77824 B

__global__ void __launch_bounds__(256, 2) gemm1_kernel(const float* __restrict__ feat,
                                                       const float* __restrict__ W1) {
    extern __shared__ float sm[];
    float* Abuf[2] = { sm, sm + A_ST };
    float* Wbuf[2] = { sm + 2 * A_ST, sm + 2 * A_ST + W_ST };

    const int tid  = threadIdx.x;
    const int node0 = blockIdx.x * 256;
    const int w    = tid >> 5;
    const int lane = tid & 31;
    const int g    = lane >> 2;     // mma group id
    const int tg   = lane & 3;      // thread-in-group
    const int wb   = w * 32;        // warp's local node base

    // global->smem mapping: thread covers rows r0l+32i (i<8), 16B col segment l3
    const int l3  = tid & 7;
    const int r0l = tid >> 3;

    float acc[2][2][4];
#pragma unroll
    for (int mt = 0; mt < 2; mt++)
#pragma unroll
        for (int nt = 0; nt < 2; nt++)
#pragma unroll
            for (int j = 0; j < 4; j++) acc[mt][nt][j] = 0.0f;

    float rA[32], rW0, rW1;
    const int wr0 = tid >> 4, wc0 = tid & 15;
    const int wr1 = (tid + 256) >> 4;

#define LOAD_REGS(cc)                                                             \
    {                                                                             \
        const int k0 = (cc) * 32;                                                 \
        _Pragma("unroll")                                                         \
        for (int i = 0; i < 8; i++) {                                             \
            int n = node0 + r0l + 32 * i;                                         \
            const float* src = feat + (size_t)n * KF + k0 + l3 * 4;               \
            _Pragma("unroll")                                                     \
            for (int j = 0; j < 4; j++) {                                         \
                int kk = k0 + l3 * 4 + j;                                         \
                rA[i * 4 + j] = (n < NN && kk < KF) ? src[j] : 0.0f;              \
            }                                                                     \
        }                                                                         \
        rW0 = (k0 + wr0 < KF) ? W1[(k0 + wr0) * NH + wc0] : 0.0f;                 \
        rW1 = (k0 + wr1 < KF) ? W1[(k0 + wr1) * NH + wc0] : 0.0f;                 \
    }

#define STORE_SMEM(b)                                                             \
    {                                                                             \
        _Pragma("unroll")                                                         \
        for (int i = 0; i < 8; i++) {                                             \
            float4 v = make_float4(rA[4 * i], rA[4 * i + 1],                      \
                                   rA[4 * i + 2], rA[4 * i + 3]);                 \
            *(float4*)&Abuf[b][(r0l + 32 * i) * APITCH + l3 * 4] = v;             \
        }                                                                         \
        Wbuf[b][tid] = rW0;                                                       \
        Wbuf[b][tid + 256] = rW1;                                                 \
    }

    const int NCHUNK = (KF + 31) / 32;   // 45

    LOAD_REGS(0);
    STORE_SMEM(0);
    __syncthreads();

    for (int c = 0; c < NCHUNK; c++) {
        const int buf = c & 1;
        const bool more = (c + 1 < NCHUNK);
        if (more) LOAD_REGS(c + 1);

        const float* A = Abuf[buf];
        const float* W = Wbuf[buf];
#pragma unroll
        for (int s = 0; s < 4; s++) {
            unsigned ahi[2][4], alo[2][4];
#pragma unroll
            for (int mt = 0; mt < 2; mt++) {
                int r0 = (wb + 16 * mt + g) * APITCH + s * 8 + tg;
                int r1 = r0 + 8 * APITCH;
                split_tf32(A[r0],     ahi[mt][0], alo[mt][0]);
                split_tf32(A[r1],     ahi[mt][1], alo[mt][1]);
                split_tf32(A[r0 + 4], ahi[mt][2], alo[mt][2]);
                split_tf32(A[r1 + 4], ahi[mt][3], alo[mt][3]);
            }
            unsigned bhi[2][2], blo[2][2];
#pragma unroll
            for (int nt = 0; nt < 2; nt++) {
                int b0 = (s * 8 + tg) * 16 + nt * 8 + g;
                split_tf32(W[b0],      bhi[nt][0], blo[nt][0]);
                split_tf32(W[b0 + 64], bhi[nt][1], blo[nt][1]);  // +4 rows
            }
#pragma unroll
            for (int mt = 0; mt < 2; mt++)
#pragma unroll
                for (int nt = 0; nt < 2; nt++) {
                    mma_tf32(acc[mt][nt], ahi[mt], bhi[nt]);
                    mma_tf32(acc[mt][nt], ahi[mt], blo[nt]);
                    mma_tf32(acc[mt][nt], alo[mt], bhi[nt]);
                }
        }
        __syncthreads();
        if (more) {
            STORE_SMEM(buf ^ 1);
            __syncthreads();
        }
    }

    // epilogue: D[g+16mt(+8)][2tg(+1) + 8nt] per mma layout; store float2
#pragma unroll
    for (int mt = 0; mt < 2; mt++) {
        int n0 = node0 + wb + 16 * mt + g;
        int n1 = n0 + 8;
#pragma unroll
        for (int nt = 0; nt < 2; nt++) {
            int col = nt * 8 + 2 * tg;
            if (n0 < NN)
                *(float2*)&g_x1[n0 * 16 + col] = make_float2(acc[mt][nt][0], acc[mt][nt][1]);
            if (n1 < NN)
                *(float2*)&g_x1[n1 * 16 + col] = make_float2(acc[mt][nt][2], acc[mt][nt][3]);
        }
    }
#undef LOAD_REGS
#undef STORE_SMEM
}

// ---------------- scatter layer 1: m1[dst] += ns[src]*x1_raw[src] ----------
__global__ void scatter1_kernel() {
    int e = blockIdx.x * blockDim.x + threadIdx.x;
    if (e >= NE) return;
    int s = g_src[e];
    int d = g_dst[e];
    float ns = g_deg_out[s];   // norm_src (L2-resident, 400KB)
    const float4* x = (const float4*)(g_x1 + s * 16);
    float* m = g_m1 + d * 16;
    float4 v0 = x[0], v1 = x[1], v2 = x[2], v3 = x[3];
    v0.x *= ns; v0.y *= ns; v0.z *= ns; v0.w *= ns;
    v1.x *= ns; v1.y *= ns; v1.z *= ns; v1.w *= ns;
    v2.x *= ns; v2.y *= ns; v2.z *= ns; v2.w *= ns;
    v3.x *= ns; v3.y *= ns; v3.z *= ns; v3.w *= ns;
    red4(m, v0);
    red4(m + 4, v1);
    red4(m + 8, v2);
    red4(m + 12, v3);
}

// ---------------- mid: h = relu(m1*nd + b1); x2 = (h*ns) @ W2 (pad to 8) ---
__global__ void mid_kernel(const float* __restrict__ b1, const float* __restrict__ W2) {
    int n = blockIdx.x * blockDim.x + threadIdx.x;
    if (n >= NN) return;
    float nd = g_deg_in[n];   // norm_dst
    float ns = g_deg_out[n];  // norm_src
    float h[16];
    const float4* mp = (const float4*)(g_m1 + n * 16);
#pragma unroll
    for (int q = 0; q < 4; q++) {
        float4 v = mp[q];
        h[4 * q + 0] = fmaxf(v.x * nd + __ldg(&b1[4 * q + 0]), 0.0f);
        h[4 * q + 1] = fmaxf(v.y * nd + __ldg(&b1[4 * q + 1]), 0.0f);
        h[4 * q + 2] = fmaxf(v.z * nd + __ldg(&b1[4 * q + 2]), 0.0f);
        h[4 * q + 3] = fmaxf(v.w * nd + __ldg(&b1[4 * q + 3]), 0.0f);
    }
    float o[8];
#pragma unroll
    for (int c = 0; c < NO; c++) {
        float s = 0.0f;
#pragma unroll
        for (int j = 0; j < 16; j++) s = fmaf(h[j], __ldg(&W2[j * NO + c]), s);
        o[c] = ns * s;
    }
    o[7] = 0.0f;
    float4* xp = (float4*)(g_x2 + n * 8);
    xp[0] = make_float4(o[0], o[1], o[2], o[3]);
    xp[1] = make_float4(o[4], o[5], o[6], o[7]);
}

// ---------------- scatter layer 2: m2[dst] += x2[src] (8 floats) -----------
__global__ void scatter2_kernel() {
    int e = blockIdx.x * blockDim.x + threadIdx.x;
    if (e >= NE) return;
    int s = g_src[e];
    int d = g_dst[e];
    const float4* x = (const float4*)(g_x2 + s * 8);
    float* m = g_m2 + d * 8;
    float4 v0 = x[0], v1 = x[1];
    red4(m, v0);
    red4(m + 4, v1);
}

// ---------------- output: out = m2*nd + b2 ---------------------------------
__global__ void out_kernel(const float* __restrict__ b2, float* __restrict__ out) {
    int i = blockIdx.x * blockDim.x + threadIdx.x;
    if (i >= NN * NO) return;
    int n = i / NO;
    int c = i - n * NO;
    out[i] = g_m2[n * 8 + c] * g_deg_in[n] + __ldg(&b2[c]);
}

// ---------------- launch ---------------------------------------------------
extern "C" void kernel_launch(void* const* d_in, const int* in_sizes, int n_in,
                              void* d_out, int out_size) {
    const float* feat = (const float*)d_in[0];
    const void* ei    = d_in[1];
    const float* W1   = (const float*)d_in[2];
    const float* b1   = (const float*)d_in[3];
    const float* W2   = (const float*)d_in[4];
    const float* b2   = (const float*)d_in[5];
    float* out        = (float*)d_out;

    // one-time host-side setup (first call is the non-captured correctness
    // run; no device memory is allocated here)
    static cudaStream_t s2 = 0;
    static cudaEvent_t evA = 0, evB = 0;
    if (!s2) {
        cudaStreamCreateWithFlags(&s2, cudaStreamNonBlocking);
        cudaEventCreateWithFlags(&evA, cudaEventDisableTiming);
        cudaEventCreateWithFlags(&evB, cudaEventDisableTiming);
        cudaFuncSetAttribute(gemm1_kernel,
                             cudaFuncAttributeMaxDynamicSharedMemorySize, SMEM_BYTES);
    }

    void *pdo, *pdi, *pm1, *pm2;
    cudaGetSymbolAddress(&pdo, g_deg_out);
    cudaGetSymbolAddress(&pdi, g_deg_in);
    cudaGetSymbolAddress(&pm1, g_m1);
    cudaGetSymbolAddress(&pm2, g_m2);
    cudaMemsetAsync(pdo, 0, (size_t)NN * sizeof(float));
    cudaMemsetAsync(pdi, 0, (size_t)NN * sizeof(float));
    cudaMemsetAsync(pm1, 0, (size_t)NN * 16 * sizeof(float));
    cudaMemsetAsync(pm2, 0, (size_t)NN * 8 * sizeof(float));

    const int TB = 256;
    const int EBLK = NE / TB;             // 12500 (exact)
    const int NBLK = (NN + TB - 1) / TB;  // 391

    // fork: edge chain on s2, gemm1 on main stream
    cudaEventRecord(evA, 0);
    cudaStreamWaitEvent(s2, evA, 0);
    detect_kernel<<<1, 32, 0, s2>>>(ei);
    convdeg_kernel<<<EBLK, TB, 0, s2>>>(ei);
    norm_kernel<<<NBLK, TB, 0, s2>>>();
    cudaEventRecord(evB, s2);

    gemm1_kernel<<<NBLK, TB, SMEM_BYTES>>>(feat, W1);

    // join (scatter1 needs src/dst, norms, and x1)
    cudaStreamWaitEvent(0, evB, 0);
    scatter1_kernel<<<EBLK, TB>>>();
    mid_kernel<<<NBLK, TB>>>(b1, W2);
    scatter2_kernel<<<EBLK, TB>>>();
    out_kernel<<<(NN * NO + TB - 1) / TB, TB>>>(b2, out);
}